// round 2
// baseline (speedup 1.0000x reference)
#include <cuda_runtime.h>
#include <cstdint>

#define NBATCH 65536
#define WARPS_PER_BLOCK 8
#define NBLOCKS 2048

// shared memory float offsets
#define WQ_OFF 0
#define WK_OFF 1152
#define WV_OFF 2304
#define WO_OFF 3456
#define W1_OFF 4608      // [32][68]
#define W2_OFF 6784      // [64][36]
#define BQ_OFF 9088
#define BK_OFF 9120
#define BV_OFF 9152
#define BO_OFF 9184
#define B1_OFF 9216
#define B2_OFF 9280
#define ARENA_OFF 9312
#define ARENA_PER_WARP 2304     // floats per warp
#define SMEM_FLOATS (ARENA_OFF + WARPS_PER_BLOCK * ARENA_PER_WARP)
#define SMEM_BYTES (SMEM_FLOATS * 4)

__device__ __forceinline__ unsigned f2tf(float x) {
    unsigned r;
    asm("cvt.rna.tf32.f32 %0, %1;" : "=r"(r) : "f"(x));
    return r;
}

__device__ __forceinline__ void mma_tf32(float c[4], const unsigned a[4],
                                         unsigned b0, unsigned b1) {
    asm volatile(
        "mma.sync.aligned.m16n8k8.row.col.f32.tf32.tf32.f32 "
        "{%0,%1,%2,%3}, {%4,%5,%6,%7}, {%8,%9}, {%0,%1,%2,%3};\n"
        : "+f"(c[0]), "+f"(c[1]), "+f"(c[2]), "+f"(c[3])
        : "r"(a[0]), "r"(a[1]), "r"(a[2]), "r"(a[3]), "r"(b0), "r"(b1));
}

// store a (v0, v1) pair as tf32-rounded floats (contiguous)
__device__ __forceinline__ void store2tf(float* p, float v0, float v1) {
    uint2 u;
    u.x = f2tf(v0);
    u.y = f2tf(v1);
    *reinterpret_cast<uint2*>(p) = u;
}

__global__ void __launch_bounds__(256, 2) tinyformer_kernel(
    const float* __restrict__ x,
    const float* __restrict__ Wq, const float* __restrict__ bq,
    const float* __restrict__ Wk, const float* __restrict__ bk,
    const float* __restrict__ Wv, const float* __restrict__ bv,
    const float* __restrict__ Wo, const float* __restrict__ bo,
    const float* __restrict__ W1, const float* __restrict__ b1,
    const float* __restrict__ W2, const float* __restrict__ b2,
    float* __restrict__ out)
{
    extern __shared__ float sm[];
    const int tid = threadIdx.x;

    // ---- load weights into smem, tf32-rounded, padded strides ----
    for (int i = tid; i < 1024; i += 256) {
        int r = i >> 5, c = i & 31;
        sm[WQ_OFF + r * 36 + c] = __uint_as_float(f2tf(Wq[i]));
        sm[WK_OFF + r * 36 + c] = __uint_as_float(f2tf(Wk[i]));
        sm[WV_OFF + r * 36 + c] = __uint_as_float(f2tf(Wv[i]));
        sm[WO_OFF + r * 36 + c] = __uint_as_float(f2tf(Wo[i]));
    }
    for (int i = tid; i < 2048; i += 256) {
        int r1 = i >> 6, c1 = i & 63;
        sm[W1_OFF + r1 * 68 + c1] = __uint_as_float(f2tf(W1[i]));
        int r2 = i >> 5, c2 = i & 31;
        sm[W2_OFF + r2 * 36 + c2] = __uint_as_float(f2tf(W2[i]));
    }
    if (tid < 32) {
        sm[BQ_OFF + tid] = bq[tid];
        sm[BK_OFF + tid] = bk[tid];
        sm[BV_OFF + tid] = bv[tid];
        sm[BO_OFF + tid] = bo[tid];
        sm[B2_OFF + tid] = b2[tid];
    }
    if (tid < 64) sm[B1_OFF + tid] = b1[tid];
    __syncthreads();

    const int lane = tid & 31, wid = tid >> 5;
    const int gid = lane >> 2, tig = lane & 3;   // mma groupID / threadID_in_group

    float* A_ = sm + ARENA_OFF + wid * ARENA_PER_WARP;
    float* Xs = A_;          // [16][36] x (exact f32)
    float* Ks = A_ + 576;    // [16][36] k (tf32)
    float* Vs = A_ + 1152;   // [16][36] v (tf32)
    float* Qs = A_ + 1728;   // [16][36] q (tf32)
    float* ATT = Ks;         // [16][20] attn probs (overlays K, dead after scores)
    float* Hs = Xs;          // [16][68] h (overlays X+K, dead after y formed)
    float* Ys = Vs;          // [16][36] y exact (overlays V)
    float* CTs = Qs;         // [16][36] context (overlays Q)

    for (int b = blockIdx.x * WARPS_PER_BLOCK + wid; b < NBATCH;
         b += gridDim.x * WARPS_PER_BLOCK) {

        // ---- load x tile [16][32] -> smem (exact) ----
        const float4* xg = reinterpret_cast<const float4*>(x + (size_t)b * 512);
#pragma unroll
        for (int i = 0; i < 4; i++) {
            float4 v = xg[lane + 32 * i];
            int e = (lane + 32 * i) << 2;
            *reinterpret_cast<float4*>(Xs + (e >> 5) * 36 + (e & 31)) = v;
        }
        __syncwarp();

        // ---- x A-fragments (tf32) : 4 k-chunks ----
        unsigned xa[4][4];
#pragma unroll
        for (int ch = 0; ch < 4; ch++) {
            int c0 = tig + 8 * ch;
            xa[ch][0] = f2tf(Xs[gid * 36 + c0]);
            xa[ch][1] = f2tf(Xs[(gid + 8) * 36 + c0]);
            xa[ch][2] = f2tf(Xs[gid * 36 + c0 + 4]);
            xa[ch][3] = f2tf(Xs[(gid + 8) * 36 + c0 + 4]);
        }

        // ---- QKV projections: [16,32] @ [32,32] x3 ----
        {
            float cq[4][4] = {}, ck[4][4] = {}, cv[4][4] = {};
#pragma unroll
            for (int ch = 0; ch < 4; ch++) {
#pragma unroll
                for (int nt = 0; nt < 4; nt++) {
                    int i0 = (tig + 8 * ch) * 36 + gid + 8 * nt;
                    int i1 = (tig + 4 + 8 * ch) * 36 + gid + 8 * nt;
                    mma_tf32(cq[nt], xa[ch], __float_as_uint(sm[WQ_OFF + i0]),
                             __float_as_uint(sm[WQ_OFF + i1]));
                    mma_tf32(ck[nt], xa[ch], __float_as_uint(sm[WK_OFF + i0]),
                             __float_as_uint(sm[WK_OFF + i1]));
                    mma_tf32(cv[nt], xa[ch], __float_as_uint(sm[WV_OFF + i0]),
                             __float_as_uint(sm[WV_OFF + i1]));
                }
            }
#pragma unroll
            for (int nt = 0; nt < 4; nt++) {
                int col = 8 * nt + 2 * tig;
                float2 bbq = *(const float2*)&sm[BQ_OFF + col];
                float2 bbk = *(const float2*)&sm[BK_OFF + col];
                float2 bbv = *(const float2*)&sm[BV_OFF + col];
                store2tf(Qs + gid * 36 + col, cq[nt][0] + bbq.x, cq[nt][1] + bbq.y);
                store2tf(Qs + (gid + 8) * 36 + col, cq[nt][2] + bbq.x, cq[nt][3] + bbq.y);
                store2tf(Ks + gid * 36 + col, ck[nt][0] + bbk.x, ck[nt][1] + bbk.y);
                store2tf(Ks + (gid + 8) * 36 + col, ck[nt][2] + bbk.x, ck[nt][3] + bbk.y);
                store2tf(Vs + gid * 36 + col, cv[nt][0] + bbv.x, cv[nt][1] + bbv.y);
                store2tf(Vs + (gid + 8) * 36 + col, cv[nt][2] + bbv.x, cv[nt][3] + bbv.y);
            }
        }
        __syncwarp();

        // ---- scores = q @ k^T / sqrt(D) : [16,16] ----
        float st[2][4] = {};
#pragma unroll
        for (int ch = 0; ch < 4; ch++) {
            unsigned qa[4];
            int c0 = tig + 8 * ch;
            qa[0] = __float_as_uint(Qs[gid * 36 + c0]);
            qa[1] = __float_as_uint(Qs[(gid + 8) * 36 + c0]);
            qa[2] = __float_as_uint(Qs[gid * 36 + c0 + 4]);
            qa[3] = __float_as_uint(Qs[(gid + 8) * 36 + c0 + 4]);
#pragma unroll
            for (int nt = 0; nt < 2; nt++) {
                unsigned b0 = __float_as_uint(Ks[(gid + 8 * nt) * 36 + tig + 8 * ch]);
                unsigned b1 = __float_as_uint(Ks[(gid + 8 * nt) * 36 + tig + 4 + 8 * ch]);
                mma_tf32(st[nt], qa, b0, b1);
            }
        }

        // ---- softmax over key dim (rows r0 = gid and gid+8) ----
        {
            const float sc = 0.17677669529663687f;  // 1/sqrt(32)
#pragma unroll
            for (int j = 0; j < 2; j++)
#pragma unroll
                for (int i = 0; i < 4; i++) st[j][i] *= sc;

            float mlo = fmaxf(fmaxf(st[0][0], st[0][1]), fmaxf(st[1][0], st[1][1]));
            float mhi = fmaxf(fmaxf(st[0][2], st[0][3]), fmaxf(st[1][2], st[1][3]));
            mlo = fmaxf(mlo, __shfl_xor_sync(0xffffffffu, mlo, 1));
            mlo = fmaxf(mlo, __shfl_xor_sync(0xffffffffu, mlo, 2));
            mhi = fmaxf(mhi, __shfl_xor_sync(0xffffffffu, mhi, 1));
            mhi = fmaxf(mhi, __shfl_xor_sync(0xffffffffu, mhi, 2));

            float p[2][4];
#pragma unroll
            for (int j = 0; j < 2; j++) {
                p[j][0] = __expf(st[j][0] - mlo);
                p[j][1] = __expf(st[j][1] - mlo);
                p[j][2] = __expf(st[j][2] - mhi);
                p[j][3] = __expf(st[j][3] - mhi);
            }
            float slo = p[0][0] + p[0][1] + p[1][0] + p[1][1];
            float shi = p[0][2] + p[0][3] + p[1][2] + p[1][3];
            slo += __shfl_xor_sync(0xffffffffu, slo, 1);
            slo += __shfl_xor_sync(0xffffffffu, slo, 2);
            shi += __shfl_xor_sync(0xffffffffu, shi, 1);
            shi += __shfl_xor_sync(0xffffffffu, shi, 2);
            float ilo = __fdividef(1.0f, slo);
            float ihi = __fdividef(1.0f, shi);

            __syncwarp();  // all K reads done before ATT (overlays K) is written
#pragma unroll
            for (int j = 0; j < 2; j++) {
                int col = 8 * j + 2 * tig;
                store2tf(ATT + gid * 20 + col, p[j][0] * ilo, p[j][1] * ilo);
                store2tf(ATT + (gid + 8) * 20 + col, p[j][2] * ihi, p[j][3] * ihi);
            }
        }
        __syncwarp();

        // ---- context = attn @ v : [16,32] ----
        {
            float ct[4][4] = {};
#pragma unroll
            for (int ch = 0; ch < 2; ch++) {
                unsigned aa[4];
                int c0 = tig + 8 * ch;
                aa[0] = __float_as_uint(ATT[gid * 20 + c0]);
                aa[1] = __float_as_uint(ATT[(gid + 8) * 20 + c0]);
                aa[2] = __float_as_uint(ATT[gid * 20 + c0 + 4]);
                aa[3] = __float_as_uint(ATT[(gid + 8) * 20 + c0 + 4]);
#pragma unroll
                for (int nt = 0; nt < 4; nt++) {
                    unsigned b0 = __float_as_uint(Vs[(tig + 8 * ch) * 36 + gid + 8 * nt]);
                    unsigned b1 = __float_as_uint(Vs[(tig + 4 + 8 * ch) * 36 + gid + 8 * nt]);
                    mma_tf32(ct[nt], aa, b0, b1);
                }
            }
            __syncwarp();  // V reads done (Y will overlay V later)
#pragma unroll
            for (int nt = 0; nt < 4; nt++) {
                int col = 8 * nt + 2 * tig;
                store2tf(CTs + gid * 36 + col, ct[nt][0], ct[nt][1]);
                store2tf(CTs + (gid + 8) * 36 + col, ct[nt][2], ct[nt][3]);
            }
        }
        __syncwarp();

        // ---- O projection + residual 1 : y = x + ctx @ Wo + bo (exact f32) ----
        {
            float oc[4][4] = {};
#pragma unroll
            for (int ch = 0; ch < 4; ch++) {
                unsigned aa[4];
                int c0 = tig + 8 * ch;
                aa[0] = __float_as_uint(CTs[gid * 36 + c0]);
                aa[1] = __float_as_uint(CTs[(gid + 8) * 36 + c0]);
                aa[2] = __float_as_uint(CTs[gid * 36 + c0 + 4]);
                aa[3] = __float_as_uint(CTs[(gid + 8) * 36 + c0 + 4]);
#pragma unroll
                for (int nt = 0; nt < 4; nt++) {
                    unsigned b0 = __float_as_uint(sm[WO_OFF + (tig + 8 * ch) * 36 + gid + 8 * nt]);
                    unsigned b1 = __float_as_uint(sm[WO_OFF + (tig + 4 + 8 * ch) * 36 + gid + 8 * nt]);
                    mma_tf32(oc[nt], aa, b0, b1);
                }
            }
#pragma unroll
            for (int nt = 0; nt < 4; nt++) {
                int col = 8 * nt + 2 * tig;
                float2 bb = *(const float2*)&sm[BO_OFF + col];
                float2 x0 = *(const float2*)&Xs[gid * 36 + col];
                float2 x1 = *(const float2*)&Xs[(gid + 8) * 36 + col];
                *(float2*)&Ys[gid * 36 + col] =
                    make_float2(oc[nt][0] + bb.x + x0.x, oc[nt][1] + bb.y + x0.y);
                *(float2*)&Ys[(gid + 8) * 36 + col] =
                    make_float2(oc[nt][2] + bb.x + x1.x, oc[nt][3] + bb.y + x1.y);
            }
        }
        __syncwarp();

        // ---- FFN1: h = relu(y @ W1 + b1) : [16,64] ----
        {
            float hc[8][4] = {};
#pragma unroll
            for (int ch = 0; ch < 4; ch++) {
                unsigned aa[4];
                int c0 = tig + 8 * ch;
                aa[0] = f2tf(Ys[gid * 36 + c0]);
                aa[1] = f2tf(Ys[(gid + 8) * 36 + c0]);
                aa[2] = f2tf(Ys[gid * 36 + c0 + 4]);
                aa[3] = f2tf(Ys[(gid + 8) * 36 + c0 + 4]);
#pragma unroll
                for (int nt = 0; nt < 8; nt++) {
                    unsigned b0 = __float_as_uint(sm[W1_OFF + (tig + 8 * ch) * 68 + gid + 8 * nt]);
                    unsigned b1 = __float_as_uint(sm[W1_OFF + (tig + 4 + 8 * ch) * 68 + gid + 8 * nt]);
                    mma_tf32(hc[nt], aa, b0, b1);
                }
            }
            __syncwarp();  // X reads (residual) done before H (overlays X) written
#pragma unroll
            for (int nt = 0; nt < 8; nt++) {
                int col = 8 * nt + 2 * tig;
                float2 bb = *(const float2*)&sm[B1_OFF + col];
                store2tf(Hs + gid * 68 + col, fmaxf(hc[nt][0] + bb.x, 0.0f),
                         fmaxf(hc[nt][1] + bb.y, 0.0f));
                store2tf(Hs + (gid + 8) * 68 + col, fmaxf(hc[nt][2] + bb.x, 0.0f),
                         fmaxf(hc[nt][3] + bb.y, 0.0f));
            }
        }
        __syncwarp();

        // ---- FFN2 + residual 2: z = y + h @ W2 + b2 -> gmem ----
        {
            float zc[4][4] = {};
#pragma unroll
            for (int ch = 0; ch < 8; ch++) {
                unsigned aa[4];
                int c0 = tig + 8 * ch;
                aa[0] = __float_as_uint(Hs[gid * 68 + c0]);
                aa[1] = __float_as_uint(Hs[(gid + 8) * 68 + c0]);
                aa[2] = __float_as_uint(Hs[gid * 68 + c0 + 4]);
                aa[3] = __float_as_uint(Hs[(gid + 8) * 68 + c0 + 4]);
#pragma unroll
                for (int nt = 0; nt < 4; nt++) {
                    unsigned b0 = __float_as_uint(sm[W2_OFF + (tig + 8 * ch) * 36 + gid + 8 * nt]);
                    unsigned b1 = __float_as_uint(sm[W2_OFF + (tig + 4 + 8 * ch) * 36 + gid + 8 * nt]);
                    mma_tf32(zc[nt], aa, b0, b1);
                }
            }
            float* og = out + (size_t)b * 512;
#pragma unroll
            for (int nt = 0; nt < 4; nt++) {
                int col = 8 * nt + 2 * tig;
                float2 bb = *(const float2*)&sm[B2_OFF + col];
                float2 y0 = *(const float2*)&Ys[gid * 36 + col];
                float2 y1 = *(const float2*)&Ys[(gid + 8) * 36 + col];
                *(float2*)&og[gid * 32 + col] =
                    make_float2(zc[nt][0] + bb.x + y0.x, zc[nt][1] + bb.y + y0.y);
                *(float2*)&og[(gid + 8) * 32 + col] =
                    make_float2(zc[nt][2] + bb.x + y1.x, zc[nt][3] + bb.y + y1.y);
            }
        }
        __syncwarp();
    }
}

extern "C" void kernel_launch(void* const* d_in, const int* in_sizes, int n_in,
                              void* d_out, int out_size) {
    cudaFuncSetAttribute(tinyformer_kernel,
                         cudaFuncAttributeMaxDynamicSharedMemorySize, SMEM_BYTES);
    tinyformer_kernel<<<NBLOCKS, 256, SMEM_BYTES>>>(
        (const float*)d_in[0],
        (const float*)d_in[1], (const float*)d_in[2],
        (const float*)d_in[3], (const float*)d_in[4],
        (const float*)d_in[5], (const float*)d_in[6],
        (const float*)d_in[7], (const float*)d_in[8],
        (const float*)d_in[9], (const float*)d_in[10],
        (const float*)d_in[11], (const float*)d_in[12],
        (float*)d_out);
}